// round 7
// baseline (speedup 1.0000x reference)
#include <cuda_runtime.h>
#include <cuda_bf16.h>
#include <mma.h>
#include <cstdint>

using namespace nvcuda;

#define NB 16
#define NL 8192
#define ND 256
#define NH 4
#define HID 128
#define QKV_LD 384

typedef unsigned long long ull;
typedef unsigned int u32;

// ---------------- scratch (device globals; no allocation) ----------------
__device__ __nv_bfloat16 g_Xhi[(size_t)NB * NL * 256];   // x split hi (64MB)
__device__ __nv_bfloat16 g_Xlo[(size_t)NB * NL * 256];   // x split lo (64MB)
__device__ float g_Sp[(size_t)NB * NH * 64 * 1024];      // per-CTA partial S (16MB)
__device__ float g_Zp[NB * NH * 64 * 32];                // per-CTA partial Z
__device__ float g_ctx[NB * NH * 32 * 32];               // context
__device__ float g_M[NB * HID * ND];                     // M[b]
__device__ float g_N[NB * ND * ND];                      // N[b]
__device__ __nv_bfloat16 g_W1hi[256 * 256];              // permuted Wkv^T hi [n'][k]
__device__ __nv_bfloat16 g_W1lo[256 * 256];
__device__ __nv_bfloat16 g_W3hi[NB * 256 * 256];         // N[b]^T hi [b][j][i]
__device__ __nv_bfloat16 g_W3lo[NB * 256 * 256];

// ---------------- helpers ----------------
__device__ __forceinline__ u32 smem_u32(const void* p) {
    u32 a;
    asm("{ .reg .u64 t; cvta.to.shared.u64 t, %1; cvt.u32.u64 %0, t; }" : "=r"(a) : "l"(p));
    return a;
}
__device__ __forceinline__ void cp16(u32 dst, const void* src) {
    asm volatile("cp.async.cg.shared.global [%0], [%1], 16;" :: "r"(dst), "l"(src) : "memory");
}
__device__ __forceinline__ void cp_commit() { asm volatile("cp.async.commit_group;" ::: "memory"); }
template<int N> __device__ __forceinline__ void cp_wait() {
    asm volatile("cp.async.wait_group %0;" :: "n"(N) : "memory");
}
__device__ __forceinline__ ull pk2(float x, float y) {
    ull r; asm("mov.b64 %0, {%1,%2};" : "=l"(r) : "f"(x), "f"(y)); return r;
}
__device__ __forceinline__ ull fma2(ull a, ull b, ull c) {
    ull d; asm("fma.rn.f32x2 %0, %1, %2, %3;" : "=l"(d) : "l"(a), "l"(b), "l"(c)); return d;
}
__device__ __forceinline__ ull add2(ull a, ull b) {
    ull d; asm("add.rn.f32x2 %0, %1, %2;" : "=l"(d) : "l"(a), "l"(b)); return d;
}
__device__ __forceinline__ void upk2(ull v, float& a, float& b) {
    asm("mov.b64 {%0,%1}, %2;" : "=f"(a), "=f"(b) : "l"(v));
}

// SMEM stage layout: k-chunk 32, row stride 40 bf16 = 80B (20 words -> LDSM conflict-free)
#define RS 40
#define O_AH 0
#define O_AL 10240
#define O_BH 20480
#define O_BL 30720
#define SZ_ST 40960
#define SMEM_DYN 81920    // 2 stages; epilogue Cs[128][128] f32 (64KB) unioned

// =====================================================================
// wmma bf16 split-3 GEMM, 128x128 tile, k-chunk 32, 2 CTAs/SM.
// C tile = A[128 x 256] @ B^T[tile-128 x 256].
// mode 0: B is permuted [h-pair K | h-pair V]; epilogue: exp on left 64 cols,
//         fused per-CTA partial S,Z for 2 heads. No C write.
// mode 1: epilogue adds bias, writes C.
// =====================================================================
__global__ void __launch_bounds__(256, 2) mma_gemm(
    const __nv_bfloat16* __restrict__ Ahi, const __nv_bfloat16* __restrict__ Alo, long long sA,
    const __nv_bfloat16* __restrict__ Bhi, const __nv_bfloat16* __restrict__ Blo, long long sB,
    float* __restrict__ C, long long sC,
    const float* __restrict__ bias, int mode)
{
    extern __shared__ unsigned char smem_raw[];
    float* Cs = reinterpret_cast<float*>(smem_raw);
    const u32 sbase = smem_u32(smem_raw);

    const int tid = threadIdx.x;
    const int wid = tid >> 5;
    const int wm = wid >> 1;        // 0..3  (rows, 32 each)
    const int wn = wid & 1;         // 0..1  (cols, 64 each)
    const int lblk = blockIdx.x;
    const int t = blockIdx.y;       // n-tile 0..1
    const int b = blockIdx.z;
    const int l0 = lblk * 128;

    const __nv_bfloat16* AhiB = Ahi + (size_t)b * sA + (size_t)l0 * 256;
    const __nv_bfloat16* AloB = Alo + (size_t)b * sA + (size_t)l0 * 256;
    const __nv_bfloat16* BhiB = Bhi + (size_t)b * sB + (size_t)t * 128 * 256;
    const __nv_bfloat16* BloB = Blo + (size_t)b * sB + (size_t)t * 128 * 256;

    wmma::fragment<wmma::accumulator, 16, 16, 16, float> acc[2][4];
#pragma unroll
    for (int mi = 0; mi < 2; mi++)
#pragma unroll
        for (int ni = 0; ni < 4; ni++) wmma::fill_fragment(acc[mi][ni], 0.0f);

    const int ldrow = tid >> 1;          // 0..127
    const int ldseg = tid & 1;           // 0..1; each thread covers segs {2s, 2s+1}

    auto issue_chunk = [&](int it, int st) {
        const int k0 = it * 32;
        const u32 s0 = sbase + st * SZ_ST;
#pragma unroll
        for (int i = 0; i < 2; i++) {
            const int seg = ldseg * 2 + i;              // 0..3, 16B each (row = 64B data)
            const u32 so = (u32)(ldrow * 80 + seg * 16);
            const size_t go = (size_t)ldrow * 256 + k0 + seg * 8;
            cp16(s0 + O_AH + so, AhiB + go);
            cp16(s0 + O_AL + so, AloB + go);
            cp16(s0 + O_BH + so, BhiB + go);
            cp16(s0 + O_BL + so, BloB + go);
        }
        cp_commit();
    };

    issue_chunk(0, 0);

    for (int it = 0; it < 8; it++) {
        const int st = it & 1;
        if (it < 7) issue_chunk(it + 1, st ^ 1);
        if (it < 7) cp_wait<1>(); else cp_wait<0>();
        __syncthreads();

        const __nv_bfloat16* Ah = (const __nv_bfloat16*)(smem_raw + st * SZ_ST + O_AH);
        const __nv_bfloat16* Al = (const __nv_bfloat16*)(smem_raw + st * SZ_ST + O_AL);
        const __nv_bfloat16* Bh = (const __nv_bfloat16*)(smem_raw + st * SZ_ST + O_BH);
        const __nv_bfloat16* Bl = (const __nv_bfloat16*)(smem_raw + st * SZ_ST + O_BL);

#pragma unroll
        for (int kk = 0; kk < 2; kk++) {
            wmma::fragment<wmma::matrix_a, 16, 16, 16, __nv_bfloat16, wmma::row_major> ah[2], al[2];
#pragma unroll
            for (int mi = 0; mi < 2; mi++) {
                int r = wm * 32 + mi * 16;
                wmma::load_matrix_sync(ah[mi], Ah + r * RS + kk * 16, RS);
                wmma::load_matrix_sync(al[mi], Al + r * RS + kk * 16, RS);
            }
#pragma unroll
            for (int ni = 0; ni < 4; ni++) {
                wmma::fragment<wmma::matrix_b, 16, 16, 16, __nv_bfloat16, wmma::col_major> bh, bl;
                int n = wn * 64 + ni * 16;
                wmma::load_matrix_sync(bh, Bh + n * RS + kk * 16, RS);
                wmma::load_matrix_sync(bl, Bl + n * RS + kk * 16, RS);
#pragma unroll
                for (int mi = 0; mi < 2; mi++) {
                    wmma::mma_sync(acc[mi][ni], ah[mi], bh, acc[mi][ni]);
                    wmma::mma_sync(acc[mi][ni], ah[mi], bl, acc[mi][ni]);
                    wmma::mma_sync(acc[mi][ni], al[mi], bh, acc[mi][ni]);
                }
            }
        }
        __syncthreads();
    }

    // ---- stage buffers dead; alias Cs[128][128] over them
#pragma unroll
    for (int mi = 0; mi < 2; mi++)
#pragma unroll
        for (int ni = 0; ni < 4; ni++)
            wmma::store_matrix_sync(Cs + (size_t)(wm * 32 + mi * 16) * 128 + wn * 64 + ni * 16,
                                    acc[mi][ni], 128, wmma::mem_row_major);
    __syncthreads();

    if (mode == 1) {
        float* Cb = C + (size_t)b * sC + (size_t)l0 * 256 + t * 128;
#pragma unroll
        for (int i = 0; i < 16; i++) {
            int idx = tid + i * 256;                  // 4096 float4 slots
            int row = idx >> 5, c4 = idx & 31;
            float4 v = *(const float4*)(Cs + (size_t)row * 128 + c4 * 4);
            float4 bb = __ldg((const float4*)(bias + t * 128 + c4 * 4));
            v.x += bb.x; v.y += bb.y; v.z += bb.z; v.w += bb.w;
            *(float4*)(Cb + (size_t)row * 256 + c4 * 4) = v;
        }
        return;
    }

    // ---- mode 0: exp in-place on left 64 cols (expK for head pair 2t,2t+1)
#pragma unroll
    for (int i = 0; i < 8; i++) {
        int idx = tid + i * 256;                      // 2048 float4 slots over 128x64
        int row = idx >> 4, c4 = idx & 15;
        float4 v = *(const float4*)(Cs + (size_t)row * 128 + c4 * 4);
        v.x = expf(v.x); v.y = expf(v.y); v.z = expf(v.z); v.w = expf(v.w);
        *(float4*)(Cs + (size_t)row * 128 + c4 * 4) = v;
    }
    __syncthreads();

    // ---- per-CTA partial S[hh][d][e] + Z[hh][d] for 2 local heads
    {
        const int hh = tid >> 7;                      // 0..1
        const int q = tid & 127;
        const int d0 = (q >> 3) * 2;                  // 0,2,..,30
        const int e0 = (q & 7) * 4;                   // 0,4,..,28
        ull acc2[2][2];
        acc2[0][0] = acc2[0][1] = acc2[1][0] = acc2[1][1] = 0ULL;
        ull z = 0ULL;

#pragma unroll 4
        for (int l = 0; l < 128; l++) {
            float2 ek = *(const float2*)(Cs + (size_t)l * 128 + hh * 32 + d0);
            float4 vv = *(const float4*)(Cs + (size_t)l * 128 + 64 + hh * 32 + e0);
            ull v01 = pk2(vv.x, vv.y), v23 = pk2(vv.z, vv.w);
            ull a0 = pk2(ek.x, ek.x), a1 = pk2(ek.y, ek.y);
            acc2[0][0] = fma2(a0, v01, acc2[0][0]);
            acc2[0][1] = fma2(a0, v23, acc2[0][1]);
            acc2[1][0] = fma2(a1, v01, acc2[1][0]);
            acc2[1][1] = fma2(a1, v23, acc2[1][1]);
            z = add2(z, pk2(ek.x, ek.y));
        }

        const int h = t * 2 + hh;
        float* Sp = g_Sp + (((size_t)(b * 4 + h) * 64 + lblk) * 1024);
#pragma unroll
        for (int i = 0; i < 2; i++) {
            float s0, s1, s2, s3;
            upk2(acc2[i][0], s0, s1); upk2(acc2[i][1], s2, s3);
            *(float4*)(Sp + (d0 + i) * 32 + e0) = make_float4(s0, s1, s2, s3);
        }
        if (e0 == 0) {
            float z0, z1; upk2(z, z0, z1);
            float* Zp = g_Zp + ((size_t)(b * 4 + h) * 64 + lblk) * 32;
            *(float2*)(Zp + d0) = make_float2(z0, z1);
        }
    }
}

// ---------------- split x: fp32 -> bf16 hi/lo ----------------
__global__ void __launch_bounds__(256) split_x(const float* __restrict__ x)
{
    size_t i4 = (size_t)blockIdx.x * 256 + threadIdx.x;
    float4 v = __ldg((const float4*)x + i4);
    float h0 = __bfloat162float(__float2bfloat16(v.x));
    float h1 = __bfloat162float(__float2bfloat16(v.y));
    float h2 = __bfloat162float(__float2bfloat16(v.z));
    float h3 = __bfloat162float(__float2bfloat16(v.w));
    __nv_bfloat162 hi0 = __floats2bfloat162_rn(h0, h1);
    __nv_bfloat162 hi1 = __floats2bfloat162_rn(h2, h3);
    __nv_bfloat162 lo0 = __floats2bfloat162_rn(v.x - h0, v.y - h1);
    __nv_bfloat162 lo1 = __floats2bfloat162_rn(v.z - h2, v.w - h3);
    *(uint2*)(g_Xhi + i4 * 4) = make_uint2(*(u32*)&hi0, *(u32*)&hi1);
    *(uint2*)(g_Xlo + i4 * 4) = make_uint2(*(u32*)&lo0, *(u32*)&lo1);
}

// ---------------- prep: permuted Wkv^T split ----------------
// n' layout: tile t = n'>>7, c = n'&127.
//   c <  64: expK for heads {2t, 2t+1}  (orig kv col = t*64 + c)
//   c >= 64: V    for heads {2t, 2t+1}  (orig kv col = 128 + t*64 + (c-64))
__global__ void prep_w1(const float* __restrict__ Wqkv)
{
    const int np = blockIdx.x, k = threadIdx.x;
    const int t = np >> 7, c = np & 127;
    const int orig = (c < 64) ? (t * 64 + c) : (128 + t * 64 + (c - 64));
    float w = Wqkv[k * QKV_LD + 128 + orig];
    float h = __bfloat162float(__float2bfloat16(w));
    g_W1hi[np * 256 + k] = __float2bfloat16(h);
    g_W1lo[np * 256 + k] = __float2bfloat16(w - h);
}

// ---------------- prep: N[b]^T split (tiled transpose) ----------------
__global__ void tsplit()
{
    const int b = blockIdx.z;
    const int i0 = blockIdx.y * 32, j0 = blockIdx.x * 32;
    const int tx = threadIdx.x, ty = threadIdx.y;
    __shared__ float t[32][33];
    const float* Nb = g_N + (size_t)b * 65536;
#pragma unroll
    for (int r = ty; r < 32; r += 8)
        t[r][tx] = Nb[(size_t)(i0 + r) * 256 + j0 + tx];
    __syncthreads();
    __nv_bfloat16* Whi = g_W3hi + (size_t)b * 65536;
    __nv_bfloat16* Wlo = g_W3lo + (size_t)b * 65536;
#pragma unroll
    for (int r = ty; r < 32; r += 8) {
        float v = t[tx][r];
        float h = __bfloat162float(__float2bfloat16(v));
        Whi[(size_t)(j0 + r) * 256 + i0 + tx] = __float2bfloat16(h);
        Wlo[(size_t)(j0 + r) * 256 + i0 + tx] = __float2bfloat16(v - h);
    }
}

// ---------------- small fp32 GEMM (N[b] = scale * Wq @ M[b]) ----------------
__global__ void __launch_bounds__(256) gemm_f32x2(
    const float* __restrict__ A, int lda, long long sA,
    const float* __restrict__ B, int ldb, long long sB,
    float* __restrict__ C, int ldc, long long sC,
    int K, float scale)
{
    const int b = blockIdx.z;
    A += (size_t)b * sA + (size_t)blockIdx.y * 128 * lda;
    B += (size_t)b * sB;
    C += (size_t)b * sC + (size_t)blockIdx.y * 128 * ldc + blockIdx.x * 128;
    const int n0 = blockIdx.x * 128;

    __shared__ float As[16][128];
    __shared__ float Bs[16][128];
    const int tid = threadIdx.x;
    const int tx = tid & 15;
    const int ty = tid >> 4;

    ull acc[8][4];
#pragma unroll
    for (int m = 0; m < 8; m++)
#pragma unroll
        for (int p = 0; p < 4; p++) acc[m][p] = 0ULL;

    for (int k0 = 0; k0 < K; k0 += 16) {
#pragma unroll
        for (int i = 0; i < 2; i++) {
            int f = tid + i * 256;
            int row = f >> 2, c4 = (f & 3) * 4;
            float4 av = *(const float4*)(A + (size_t)row * lda + k0 + c4);
            As[c4 + 0][row] = av.x; As[c4 + 1][row] = av.y;
            As[c4 + 2][row] = av.z; As[c4 + 3][row] = av.w;
        }
#pragma unroll
        for (int i = 0; i < 2; i++) {
            int f = tid + i * 256;
            int row = f >> 5, c = (f & 31) * 4;
            *(float4*)(&Bs[row][c]) = *(const float4*)(B + (size_t)(k0 + row) * ldb + n0 + c);
        }
        __syncthreads();
#pragma unroll
        for (int kk = 0; kk < 16; kk++) {
            float4 a0 = *(const float4*)(&As[kk][ty * 4]);
            float4 a1 = *(const float4*)(&As[kk][64 + ty * 4]);
            float4 b0 = *(const float4*)(&Bs[kk][tx * 4]);
            float4 b1 = *(const float4*)(&Bs[kk][64 + tx * 4]);
            ull bp[4] = { pk2(b0.x, b0.y), pk2(b0.z, b0.w), pk2(b1.x, b1.y), pk2(b1.z, b1.w) };
            float am[8] = { a0.x, a0.y, a0.z, a0.w, a1.x, a1.y, a1.z, a1.w };
#pragma unroll
            for (int m = 0; m < 8; m++) {
                ull ap = pk2(am[m], am[m]);
#pragma unroll
                for (int p = 0; p < 4; p++) acc[m][p] = fma2(ap, bp[p], acc[m][p]);
            }
        }
        __syncthreads();
    }

#pragma unroll
    for (int m = 0; m < 8; m++) {
        int row = (m < 4) ? (ty * 4 + m) : (64 + ty * 4 + m - 4);
        float c0, c1, c2, c3, c4, c5, c6, c7;
        upk2(acc[m][0], c0, c1); upk2(acc[m][1], c2, c3);
        upk2(acc[m][2], c4, c5); upk2(acc[m][3], c6, c7);
        *(float4*)(C + (size_t)row * ldc + tx * 4) =
            make_float4(c0 * scale, c1 * scale, c2 * scale, c3 * scale);
        *(float4*)(C + (size_t)row * ldc + 64 + tx * 4) =
            make_float4(c4 * scale, c5 * scale, c6 * scale, c7 * scale);
    }
}

// ---------------- context = (sum_cta S) / (sum_cta Z) ----------------
__global__ void __launch_bounds__(1024) ctx_kernel()
{
    const int h = blockIdx.x, b = blockIdx.y;
    const int t = threadIdx.x;
    const int d = t >> 5, e = t & 31;
    const float* Sp = g_Sp + (size_t)(b * 4 + h) * 64 * 1024;
    float s = 0.f;
#pragma unroll
    for (int sp = 0; sp < 64; sp++) s += Sp[sp * 1024 + t];
    __shared__ float zs[32];
    if (e == 0) {
        const float* Zp = g_Zp + (size_t)(b * 4 + h) * 64 * 32;
        float zz = 0.f;
#pragma unroll
        for (int sp = 0; sp < 64; sp++) zz += Zp[sp * 32 + d];
        zs[d] = zz;
    }
    __syncthreads();
    g_ctx[(size_t)(b * 4 + h) * 1024 + t] = s / zs[d];
}

// ---------------- M[b] ----------------
__global__ void __launch_bounds__(256) m_kernel(const float* __restrict__ Wout)
{
    const int b = blockIdx.x;
    const int h = blockIdx.y;
    const int j = threadIdx.x;
    __shared__ float cs[1024];
    for (int i = j; i < 1024; i += 256) cs[i] = g_ctx[(size_t)b * 4096 + h * 1024 + i];
    __syncthreads();
    float* Mb = g_M + (size_t)b * HID * ND;
    float w[32];
#pragma unroll
    for (int e = 0; e < 32; e++) w[e] = Wout[(h * 32 + e) * 256 + j];
    for (int d = 0; d < 32; d++) {
        float a = 0.f;
#pragma unroll
        for (int e = 0; e < 32; e++) a += cs[d * 32 + e] * w[e];
        Mb[(h * 32 + d) * 256 + j] = a;
    }
}

// ---------------- launch ----------------
extern "C" void kernel_launch(void* const* d_in, const int* in_sizes, int n_in,
                              void* d_out, int out_size)
{
    const float* x    = (const float*)d_in[0];
    const float* Wqkv = (const float*)d_in[1];
    const float* Wout = (const float*)d_in[2];
    const float* bout = (const float*)d_in[3];
    float* out = (float*)d_out;

    float *Mp, *Np;
    __nv_bfloat16 *xh, *xl, *w1h, *w1l, *w3h, *w3l;
    cudaGetSymbolAddress((void**)&Mp, g_M);
    cudaGetSymbolAddress((void**)&Np, g_N);
    cudaGetSymbolAddress((void**)&xh, g_Xhi);
    cudaGetSymbolAddress((void**)&xl, g_Xlo);
    cudaGetSymbolAddress((void**)&w1h, g_W1hi);
    cudaGetSymbolAddress((void**)&w1l, g_W1lo);
    cudaGetSymbolAddress((void**)&w3h, g_W3hi);
    cudaGetSymbolAddress((void**)&w3l, g_W3lo);

    cudaFuncSetAttribute(mma_gemm, cudaFuncAttributeMaxDynamicSharedMemorySize, SMEM_DYN);

    const float scale = 0.17677669529663687f;
    const long long sX = (long long)NL * ND;

    // 1) split x -> bf16 hi/lo
    split_x<<<32768, 256>>>(x);

    // 2) permuted split Wkv^T
    prep_w1<<<256, 256>>>(Wqkv);

    // 3) kv GEMM + fused exp + partial S,Z (head-pair tiled)
    mma_gemm<<<dim3(64, 2, NB), 256, SMEM_DYN>>>(
        xh, xl, sX, w1h, w1l, 0, nullptr, 0, nullptr, 0);

    // 4) context
    ctx_kernel<<<dim3(NH, NB), 1024>>>();

    // 5) M[b]
    m_kernel<<<dim3(NB, NH), 256>>>(Wout);

    // 6) N[b] = scale * Wq @ M[b]
    gemm_f32x2<<<dim3(2, 2, NB), 256>>>(
        Wqkv, QKV_LD, 0, Mp, ND, (long long)HID * ND,
        Np, ND, (long long)ND * ND, HID, scale);

    // 7) transpose+split N[b]
    tsplit<<<dim3(8, 8, NB), dim3(32, 8)>>>();

    // 8) out = x @ N[b] + b_out
    mma_gemm<<<dim3(64, 2, NB), 256, SMEM_DYN>>>(
        xh, xl, sX, w3h, w3l, 65536, out, sX, bout, 1);
}

// round 8
// speedup vs baseline: 1.4346x; 1.4346x over previous
#include <cuda_runtime.h>
#include <cuda_fp16.h>
#include <mma.h>
#include <cstdint>

using namespace nvcuda;

#define NB 16
#define NL 8192
#define ND 256
#define NH 4
#define HID 128
#define QKV_LD 384

typedef unsigned long long ull;
typedef unsigned int u32;

// ---------------- scratch (device globals; no allocation) ----------------
__device__ half g_Xh[(size_t)NB * NL * 256];             // x fp16 hi (64MB)
__device__ half g_Xl[(size_t)NB * NL * 256];             // x fp16 lo (64MB)
__device__ float g_Sp[(size_t)NB * NH * 64 * 1024];      // per-CTA partial S (16MB)
__device__ float g_Zp[NB * NH * 64 * 32];                // per-CTA partial Z
__device__ float g_ctx[NB * NH * 32 * 32];               // context
__device__ float g_M[NB * HID * ND];                     // M[b]
__device__ float g_N[NB * ND * ND];                      // N[b]
__device__ half g_W1[256 * 256];                         // Wkv^T fp16 [n][k]
__device__ half g_W3[NB * 256 * 256];                    // N[b]^T fp16 [b][j][i]

// ---------------- helpers ----------------
__device__ __forceinline__ u32 smem_u32(const void* p) {
    u32 a;
    asm("{ .reg .u64 t; cvta.to.shared.u64 t, %1; cvt.u32.u64 %0, t; }" : "=r"(a) : "l"(p));
    return a;
}
__device__ __forceinline__ void cp16(u32 dst, const void* src) {
    asm volatile("cp.async.cg.shared.global [%0], [%1], 16;" :: "r"(dst), "l"(src) : "memory");
}
__device__ __forceinline__ void cp_commit() { asm volatile("cp.async.commit_group;" ::: "memory"); }
template<int N> __device__ __forceinline__ void cp_wait() {
    asm volatile("cp.async.wait_group %0;" :: "n"(N) : "memory");
}
__device__ __forceinline__ ull pk2(float x, float y) {
    ull r; asm("mov.b64 %0, {%1,%2};" : "=l"(r) : "f"(x), "f"(y)); return r;
}
__device__ __forceinline__ ull fma2(ull a, ull b, ull c) {
    ull d; asm("fma.rn.f32x2 %0, %1, %2, %3;" : "=l"(d) : "l"(a), "l"(b), "l"(c)); return d;
}
__device__ __forceinline__ ull add2(ull a, ull b) {
    ull d; asm("add.rn.f32x2 %0, %1, %2;" : "=l"(d) : "l"(a), "l"(b)); return d;
}
__device__ __forceinline__ void upk2(ull v, float& a, float& b) {
    asm("mov.b64 {%0,%1}, %2;" : "=f"(a), "=f"(b) : "l"(v));
}

// SMEM stage layout: k-chunk 64, row stride 72 fp16 = 144B (9x16B -> LDSM conflict-free)
#define RS 72
#define O_AH 0
#define O_AL 18432
#define O_B  36864
#define SZ_ST 73728
#define SMEM_DYN 221184   // 3 stages; epilogue Cs[128][256] f32 (128KB) unioned

// =====================================================================
// wmma fp16 split-2 GEMM: C[128-tile x 256] = (Ah+Al) @ B^T.
// A = x pre-split fp16 hi/lo; B single fp16 [n][k]. 3-stage cp.async ring,
// one __syncthreads per k-iteration.
// mode 0: epilogue computes exp + per-CTA partial S,Z (no C write).
// mode 1: epilogue adds bias, writes C.
// =====================================================================
__global__ void __launch_bounds__(256) mma_gemm(
    const half* __restrict__ Ahi, const half* __restrict__ Alo, long long sA,
    const half* __restrict__ B, long long sB,
    float* __restrict__ C, long long sC,
    const float* __restrict__ bias, int mode)
{
    extern __shared__ unsigned char smem_raw[];
    float* Cs = reinterpret_cast<float*>(smem_raw);
    const u32 sbase = smem_u32(smem_raw);

    const int tid = threadIdx.x;
    const int wid = tid >> 5;
    const int wm = wid >> 2;        // 0..1 (rows, 64 each)
    const int wn = wid & 3;         // 0..3 (cols, 64 each)
    const int b = blockIdx.y;
    const int l0 = blockIdx.x * 128;

    const half* AhB = Ahi + (size_t)b * sA + (size_t)l0 * 256;
    const half* AlB = Alo + (size_t)b * sA + (size_t)l0 * 256;
    const half* BB  = B + (size_t)b * sB;

    wmma::fragment<wmma::accumulator, 16, 16, 16, float> acc[4][4];
#pragma unroll
    for (int mi = 0; mi < 4; mi++)
#pragma unroll
        for (int ni = 0; ni < 4; ni++) wmma::fill_fragment(acc[mi][ni], 0.0f);

    auto issue_chunk = [&](int it, int st) {
        const int k0 = it * 64;
        const u32 s0 = sbase + st * SZ_ST;
        // A: 128 rows x 64 k (hi+lo): 1024 16B ops per buffer
#pragma unroll
        for (int i = 0; i < 4; i++) {
            int idx = tid + i * 256;
            int row = idx >> 3, seg = idx & 7;
            size_t go = (size_t)row * 256 + k0 + seg * 8;
            u32 so = (u32)(row * 144 + seg * 16);
            cp16(s0 + O_AH + so, AhB + go);
            cp16(s0 + O_AL + so, AlB + go);
        }
        // B: 256 rows x 64 k: 2048 16B ops
#pragma unroll
        for (int i = 0; i < 8; i++) {
            int idx = tid + i * 256;
            int n = idx >> 3, seg = idx & 7;
            size_t go = (size_t)n * 256 + k0 + seg * 8;
            u32 so = (u32)(n * 144 + seg * 16);
            cp16(s0 + O_B + so, BB + go);
        }
        cp_commit();
    };

    issue_chunk(0, 0);
    issue_chunk(1, 1);

    for (int it = 0; it < 4; it++) {
        const int st = it % 3;
        if (it < 3) cp_wait<1>(); else cp_wait<0>();
        __syncthreads();                 // chunk 'it' visible; compute(it-1) done by all
        if (it < 2) issue_chunk(it + 2, (it + 2) % 3);

        const half* Ah = (const half*)(smem_raw + st * SZ_ST + O_AH);
        const half* Al = (const half*)(smem_raw + st * SZ_ST + O_AL);
        const half* Bs = (const half*)(smem_raw + st * SZ_ST + O_B);

#pragma unroll
        for (int kk = 0; kk < 4; kk++) {
            wmma::fragment<wmma::matrix_a, 16, 16, 16, half, wmma::row_major> ah[4], al[4];
            wmma::fragment<wmma::matrix_b, 16, 16, 16, half, wmma::col_major> bf[4];
#pragma unroll
            for (int mi = 0; mi < 4; mi++) {
                int r = wm * 64 + mi * 16;
                wmma::load_matrix_sync(ah[mi], Ah + r * RS + kk * 16, RS);
                wmma::load_matrix_sync(al[mi], Al + r * RS + kk * 16, RS);
            }
#pragma unroll
            for (int ni = 0; ni < 4; ni++) {
                int n = wn * 64 + ni * 16;
                wmma::load_matrix_sync(bf[ni], Bs + n * RS + kk * 16, RS);
            }
#pragma unroll
            for (int mi = 0; mi < 4; mi++)
#pragma unroll
                for (int ni = 0; ni < 4; ni++) {
                    wmma::mma_sync(acc[mi][ni], ah[mi], bf[ni], acc[mi][ni]);
                    wmma::mma_sync(acc[mi][ni], al[mi], bf[ni], acc[mi][ni]);
                }
        }
    }
    __syncthreads();   // all warps done with stage reads before Cs aliases them

    // ---- stage buffers dead; alias Cs[128][256] over them
#pragma unroll
    for (int mi = 0; mi < 4; mi++)
#pragma unroll
        for (int ni = 0; ni < 4; ni++)
            wmma::store_matrix_sync(Cs + (size_t)(wm * 64 + mi * 16) * 256 + wn * 64 + ni * 16,
                                    acc[mi][ni], 256, wmma::mem_row_major);
    __syncthreads();

    if (mode == 1) {
        float* Cb = C + (size_t)b * sC + (size_t)l0 * 256;
#pragma unroll
        for (int i = 0; i < 32; i++) {
            int idx = tid + i * 256;
            int row = idx >> 6, c4 = idx & 63;
            float4 v = *(const float4*)(Cs + (size_t)row * 256 + c4 * 4);
            float4 bb = __ldg((const float4*)(bias + c4 * 4));
            v.x += bb.x; v.y += bb.y; v.z += bb.z; v.w += bb.w;
            *(float4*)(Cb + (size_t)row * 256 + c4 * 4) = v;
        }
        return;
    }

    // ---- mode 0: exp in-place on K half (cols 0..127)
#pragma unroll
    for (int i = 0; i < 16; i++) {
        int idx = tid + i * 256;                  // 4096 float4 slots over 128x128
        int row = idx >> 5, c4 = idx & 31;
        float4 v = *(const float4*)(Cs + (size_t)row * 256 + c4 * 4);
        v.x = expf(v.x); v.y = expf(v.y); v.z = expf(v.z); v.w = expf(v.w);
        *(float4*)(Cs + (size_t)row * 256 + c4 * 4) = v;
    }
    __syncthreads();

    // ---- per-CTA partial S[h][d][e] (fp32, f32x2 packed) + Z[h][d]
    {
        const int h = tid >> 6;
        const int q = tid & 63;
        const int d0 = (q >> 3) * 4;
        const int e0 = (q & 7) * 4;
        ull acc2[4][2];
#pragma unroll
        for (int i = 0; i < 4; i++) { acc2[i][0] = 0ULL; acc2[i][1] = 0ULL; }
        ull z01 = 0ULL, z23 = 0ULL;

#pragma unroll 4
        for (int l = 0; l < 128; l++) {
            float4 ek = *(const float4*)(Cs + (size_t)l * 256 + h * 32 + d0);
            float4 vv = *(const float4*)(Cs + (size_t)l * 256 + 128 + h * 32 + e0);
            ull v01 = pk2(vv.x, vv.y), v23 = pk2(vv.z, vv.w);
            float ea[4] = { ek.x, ek.y, ek.z, ek.w };
#pragma unroll
            for (int i = 0; i < 4; i++) {
                ull ap = pk2(ea[i], ea[i]);
                acc2[i][0] = fma2(ap, v01, acc2[i][0]);
                acc2[i][1] = fma2(ap, v23, acc2[i][1]);
            }
            z01 = add2(z01, pk2(ek.x, ek.y));
            z23 = add2(z23, pk2(ek.z, ek.w));
        }

        float* Sp = g_Sp + (((size_t)(b * 4 + h) * 64 + blockIdx.x) * 1024);
#pragma unroll
        for (int i = 0; i < 4; i++) {
            float s0, s1, s2, s3;
            upk2(acc2[i][0], s0, s1); upk2(acc2[i][1], s2, s3);
            *(float4*)(Sp + (d0 + i) * 32 + e0) = make_float4(s0, s1, s2, s3);
        }
        if (e0 == 0) {
            float z0, z1, z2, z3;
            upk2(z01, z0, z1); upk2(z23, z2, z3);
            float* Zp = g_Zp + ((size_t)(b * 4 + h) * 64 + blockIdx.x) * 32;
            *(float4*)(Zp + d0) = make_float4(z0, z1, z2, z3);
        }
    }
}

// ---------------- split x: fp32 -> fp16 hi/lo ----------------
__global__ void __launch_bounds__(256) split_x(const float* __restrict__ x)
{
    size_t i4 = (size_t)blockIdx.x * 256 + threadIdx.x;
    float4 v = __ldg((const float4*)x + i4);
    half h0 = __float2half_rn(v.x), h1 = __float2half_rn(v.y);
    half h2 = __float2half_rn(v.z), h3 = __float2half_rn(v.w);
    half l0 = __float2half_rn(v.x - __half2float(h0));
    half l1 = __float2half_rn(v.y - __half2float(h1));
    half l2 = __float2half_rn(v.z - __half2float(h2));
    half l3 = __float2half_rn(v.w - __half2float(h3));
    half2 hh0 = __halves2half2(h0, h1), hh1 = __halves2half2(h2, h3);
    half2 ll0 = __halves2half2(l0, l1), ll1 = __halves2half2(l2, l3);
    *(uint2*)(g_Xh + i4 * 4) = make_uint2(*(u32*)&hh0, *(u32*)&hh1);
    *(uint2*)(g_Xl + i4 * 4) = make_uint2(*(u32*)&ll0, *(u32*)&ll1);
}

// ---------------- prep: Wkv^T fp16 ----------------
__global__ void prep_w1(const float* __restrict__ Wqkv)
{
    const int n = blockIdx.x, k = threadIdx.x;
    g_W1[n * 256 + k] = __float2half_rn(Wqkv[k * QKV_LD + 128 + n]);
}

// ---------------- prep: N[b]^T fp16 (tiled transpose) ----------------
__global__ void tsplit()
{
    const int b = blockIdx.z;
    const int i0 = blockIdx.y * 32, j0 = blockIdx.x * 32;
    const int tx = threadIdx.x, ty = threadIdx.y;
    __shared__ float t[32][33];
    const float* Nb = g_N + (size_t)b * 65536;
#pragma unroll
    for (int r = ty; r < 32; r += 8)
        t[r][tx] = Nb[(size_t)(i0 + r) * 256 + j0 + tx];
    __syncthreads();
    half* W = g_W3 + (size_t)b * 65536;
#pragma unroll
    for (int r = ty; r < 32; r += 8)
        W[(size_t)(j0 + r) * 256 + i0 + tx] = __float2half_rn(t[tx][r]);
}

// ---------------- small fp32 GEMM (N[b] = scale * Wq @ M[b]) ----------------
__global__ void __launch_bounds__(256) gemm_f32x2(
    const float* __restrict__ A, int lda, long long sA,
    const float* __restrict__ B, int ldb, long long sB,
    float* __restrict__ C, int ldc, long long sC,
    int K, float scale)
{
    const int b = blockIdx.z;
    A += (size_t)b * sA + (size_t)blockIdx.y * 128 * lda;
    B += (size_t)b * sB;
    C += (size_t)b * sC + (size_t)blockIdx.y * 128 * ldc + blockIdx.x * 128;
    const int n0 = blockIdx.x * 128;

    __shared__ float As[16][128];
    __shared__ float Bs[16][128];
    const int tid = threadIdx.x;
    const int tx = tid & 15;
    const int ty = tid >> 4;

    ull acc[8][4];
#pragma unroll
    for (int m = 0; m < 8; m++)
#pragma unroll
        for (int p = 0; p < 4; p++) acc[m][p] = 0ULL;

    for (int k0 = 0; k0 < K; k0 += 16) {
#pragma unroll
        for (int i = 0; i < 2; i++) {
            int f = tid + i * 256;
            int row = f >> 2, c4 = (f & 3) * 4;
            float4 av = *(const float4*)(A + (size_t)row * lda + k0 + c4);
            As[c4 + 0][row] = av.x; As[c4 + 1][row] = av.y;
            As[c4 + 2][row] = av.z; As[c4 + 3][row] = av.w;
        }
#pragma unroll
        for (int i = 0; i < 2; i++) {
            int f = tid + i * 256;
            int row = f >> 5, c = (f & 31) * 4;
            *(float4*)(&Bs[row][c]) = *(const float4*)(B + (size_t)(k0 + row) * ldb + n0 + c);
        }
        __syncthreads();
#pragma unroll
        for (int kk = 0; kk < 16; kk++) {
            float4 a0 = *(const float4*)(&As[kk][ty * 4]);
            float4 a1 = *(const float4*)(&As[kk][64 + ty * 4]);
            float4 b0 = *(const float4*)(&Bs[kk][tx * 4]);
            float4 b1 = *(const float4*)(&Bs[kk][64 + tx * 4]);
            ull bp[4] = { pk2(b0.x, b0.y), pk2(b0.z, b0.w), pk2(b1.x, b1.y), pk2(b1.z, b1.w) };
            float am[8] = { a0.x, a0.y, a0.z, a0.w, a1.x, a1.y, a1.z, a1.w };
#pragma unroll
            for (int m = 0; m < 8; m++) {
                ull ap = pk2(am[m], am[m]);
#pragma unroll
                for (int p = 0; p < 4; p++) acc[m][p] = fma2(ap, bp[p], acc[m][p]);
            }
        }
        __syncthreads();
    }

#pragma unroll
    for (int m = 0; m < 8; m++) {
        int row = (m < 4) ? (ty * 4 + m) : (64 + ty * 4 + m - 4);
        float c0, c1, c2, c3, c4, c5, c6, c7;
        upk2(acc[m][0], c0, c1); upk2(acc[m][1], c2, c3);
        upk2(acc[m][2], c4, c5); upk2(acc[m][3], c6, c7);
        *(float4*)(C + (size_t)row * ldc + tx * 4) =
            make_float4(c0 * scale, c1 * scale, c2 * scale, c3 * scale);
        *(float4*)(C + (size_t)row * ldc + 64 + tx * 4) =
            make_float4(c4 * scale, c5 * scale, c6 * scale, c7 * scale);
    }
}

// ---------------- context = (sum_cta S) / (sum_cta Z) ----------------
__global__ void __launch_bounds__(1024) ctx_kernel()
{
    const int h = blockIdx.x, b = blockIdx.y;
    const int t = threadIdx.x;
    const int d = t >> 5, e = t & 31;
    const float* Sp = g_Sp + (size_t)(b * 4 + h) * 64 * 1024;
    float s = 0.f;
#pragma unroll
    for (int sp = 0; sp < 64; sp++) s += Sp[sp * 1024 + t];
    __shared__ float zs[32];
    if (e == 0) {
        const float* Zp = g_Zp + (size_t)(b * 4 + h) * 64 * 32;
        float zz = 0.f;
#pragma unroll
        for (int sp = 0; sp < 64; sp++) zz += Zp[sp * 32 + d];
        zs[d] = zz;
    }
    __syncthreads();
    g_ctx[(size_t)(b * 4 + h) * 1024 + t] = s / zs[d];
}

// ---------------- M[b] ----------------
__global__ void __launch_bounds__(256) m_kernel(const float* __restrict__ Wout)
{
    const int b = blockIdx.x;
    const int h = blockIdx.y;
    const int j = threadIdx.x;
    __shared__ float cs[1024];
    for (int i = j; i < 1024; i += 256) cs[i] = g_ctx[(size_t)b * 4096 + h * 1024 + i];
    __syncthreads();
    float* Mb = g_M + (size_t)b * HID * ND;
    float w[32];
#pragma unroll
    for (int e = 0; e < 32; e++) w[e] = Wout[(h * 32 + e) * 256 + j];
    for (int d = 0; d < 32; d++) {
        float a = 0.f;
#pragma unroll
        for (int e = 0; e < 32; e++) a += cs[d * 32 + e] * w[e];
        Mb[(h * 32 + d) * 256 + j] = a;
    }
}

// ---------------- launch ----------------
extern "C" void kernel_launch(void* const* d_in, const int* in_sizes, int n_in,
                              void* d_out, int out_size)
{
    const float* x    = (const float*)d_in[0];
    const float* Wqkv = (const float*)d_in[1];
    const float* Wout = (const float*)d_in[2];
    const float* bout = (const float*)d_in[3];
    float* out = (float*)d_out;

    float *Mp, *Np;
    half *xh, *xl, *w1, *w3;
    cudaGetSymbolAddress((void**)&Mp, g_M);
    cudaGetSymbolAddress((void**)&Np, g_N);
    cudaGetSymbolAddress((void**)&xh, g_Xh);
    cudaGetSymbolAddress((void**)&xl, g_Xl);
    cudaGetSymbolAddress((void**)&w1, g_W1);
    cudaGetSymbolAddress((void**)&w3, g_W3);

    cudaFuncSetAttribute(mma_gemm, cudaFuncAttributeMaxDynamicSharedMemorySize, SMEM_DYN);

    const float scale = 0.17677669529663687f;
    const long long sX = (long long)NL * ND;

    // 1) split x -> fp16 hi/lo
    split_x<<<32768, 256>>>(x);

    // 2) Wkv^T fp16
    prep_w1<<<256, 256>>>(Wqkv);

    // 3) kv GEMM + fused exp + partial S,Z
    mma_gemm<<<dim3(64, NB), 256, SMEM_DYN>>>(
        xh, xl, sX, w1, 0, nullptr, 0, nullptr, 0);

    // 4) context
    ctx_kernel<<<dim3(NH, NB), 1024>>>();

    // 5) M[b]
    m_kernel<<<dim3(NB, NH), 256>>>(Wout);

    // 6) N[b] = scale * Wq @ M[b]
    gemm_f32x2<<<dim3(2, 2, NB), 256>>>(
        Wqkv, QKV_LD, 0, Mp, ND, (long long)HID * ND,
        Np, ND, (long long)ND * ND, HID, scale);

    // 7) transpose N[b] -> fp16
    tsplit<<<dim3(8, 8, NB), dim3(32, 8)>>>();

    // 8) out = x @ N[b] + b_out
    mma_gemm<<<dim3(64, NB), 256, SMEM_DYN>>>(
        xh, xl, sX, w3, 65536, out, sX, bout, 1);
}

// round 9
// speedup vs baseline: 1.5328x; 1.0685x over previous
#include <cuda_runtime.h>
#include <cuda_fp16.h>
#include <mma.h>
#include <cstdint>

using namespace nvcuda;

#define NB 16
#define NL 8192
#define ND 256
#define NH 4
#define HID 128
#define QKV_LD 384

typedef unsigned long long ull;
typedef unsigned int u32;

// ---------------- scratch (device globals; no allocation) ----------------
__device__ float g_Sp[(size_t)NB * NH * 64 * 1024];      // per-CTA partial S (16MB)
__device__ float g_Zp[NB * NH * 64 * 32];                // per-CTA partial Z
__device__ float g_ctx[NB * NH * 32 * 32];               // context
__device__ float g_M[NB * HID * ND];                     // M[b]
__device__ float g_N[NB * ND * ND];                      // N[b]
__device__ half g_W1[256 * 256];                         // Wkv^T fp16 [n][k]
__device__ half g_W3[NB * 256 * 256];                    // N[b]^T fp16 [b][j][i]

// ---------------- helpers ----------------
__device__ __forceinline__ u32 smem_u32(const void* p) {
    u32 a;
    asm("{ .reg .u64 t; cvta.to.shared.u64 t, %1; cvt.u32.u64 %0, t; }" : "=r"(a) : "l"(p));
    return a;
}
__device__ __forceinline__ void cp16(u32 dst, const void* src) {
    asm volatile("cp.async.cg.shared.global [%0], [%1], 16;" :: "r"(dst), "l"(src) : "memory");
}
__device__ __forceinline__ void cp_commit() { asm volatile("cp.async.commit_group;" ::: "memory"); }
template<int N> __device__ __forceinline__ void cp_wait() {
    asm volatile("cp.async.wait_group %0;" :: "n"(N) : "memory");
}
__device__ __forceinline__ void sts64(u32 addr, u32 a, u32 b) {
    asm volatile("st.shared.v2.b32 [%0], {%1,%2};" :: "r"(addr), "r"(a), "r"(b) : "memory");
}
__device__ __forceinline__ ull pk2(float x, float y) {
    ull r; asm("mov.b64 %0, {%1,%2};" : "=l"(r) : "f"(x), "f"(y)); return r;
}
__device__ __forceinline__ ull fma2(ull a, ull b, ull c) {
    ull d; asm("fma.rn.f32x2 %0, %1, %2, %3;" : "=l"(d) : "l"(a), "l"(b), "l"(c)); return d;
}
__device__ __forceinline__ ull add2(ull a, ull b) {
    ull d; asm("add.rn.f32x2 %0, %1, %2;" : "=l"(d) : "l"(a), "l"(b)); return d;
}
__device__ __forceinline__ void upk2(ull v, float& a, float& b) {
    asm("mov.b64 {%0,%1}, %2;" : "=f"(a), "=f"(b) : "l"(v));
}
__device__ __forceinline__ u32 pkh2(half a, half b) {
    half2 t = __halves2half2(a, b);
    return *reinterpret_cast<u32*>(&t);
}

// SMEM stage layout: k-chunk 64, row stride 72 fp16 = 144B (9x16B -> LDSM conflict-free)
#define RS 72
#define O_AH 0
#define O_AL 18432
#define O_B  36864
#define SZ_ST 73728
#define SMEM_DYN 221184   // 3 stages; epilogue Cs[128][256] f32 (128KB) unioned

// =====================================================================
// wmma fp16 split-2 GEMM: C[128-tile x 256] = (Ah+Al) @ B^T.
// A = fp32 x, loaded LDG.128 one chunk ahead, converted to fp16 hi/lo in
// the producer path (no pre-split pass). B single fp16 [n][k], cp.async.
// 3-stage ring, one __syncthreads per k-iteration.
// mode 0: epilogue computes exp + per-CTA partial S,Z (no C write).
// mode 1: epilogue adds bias, writes C.
// =====================================================================
__global__ void __launch_bounds__(256) mma_gemm(
    const float* __restrict__ A, long long sA,
    const half* __restrict__ B, long long sB,
    float* __restrict__ C, long long sC,
    const float* __restrict__ bias, int mode)
{
    extern __shared__ unsigned char smem_raw[];
    float* Cs = reinterpret_cast<float*>(smem_raw);
    const u32 sbase = smem_u32(smem_raw);

    const int tid = threadIdx.x;
    const int wid = tid >> 5;
    const int wm = wid >> 2;        // 0..1 (rows, 64 each)
    const int wn = wid & 3;         // 0..3 (cols, 64 each)
    const int b = blockIdx.y;
    const int l0 = blockIdx.x * 128;

    const float* AB = A + (size_t)b * sA + (size_t)l0 * 256;
    const half* BB  = B + (size_t)b * sB;

    wmma::fragment<wmma::accumulator, 16, 16, 16, float> acc[4][4];
#pragma unroll
    for (int mi = 0; mi < 4; mi++)
#pragma unroll
        for (int ni = 0; ni < 4; ni++) wmma::fill_fragment(acc[mi][ni], 0.0f);

    // per-thread A staging: 8 float4 = 32 floats of the 128x64 chunk
    const int arow = tid >> 1;                  // rows 0..127 (2 threads/row)... see idx map below
    float4 areg[8];

    auto load_A = [&](int it) {
        const int k0 = it * 64;
#pragma unroll
        for (int i = 0; i < 8; i++) {
            int idx = i * 256 + tid;            // 2048 float4 slots
            int row = idx >> 4, c4 = idx & 15;
            areg[i] = __ldg((const float4*)(AB + (size_t)row * 256 + k0 + c4 * 4));
        }
    };
    auto sts_A = [&](int st) {
        const u32 hb = sbase + st * SZ_ST + O_AH;
        const u32 lb = sbase + st * SZ_ST + O_AL;
#pragma unroll
        for (int i = 0; i < 8; i++) {
            int idx = i * 256 + tid;
            int row = idx >> 4, c4 = idx & 15;
            float4 v = areg[i];
            half hx = __float2half_rn(v.x), hy = __float2half_rn(v.y);
            half hz = __float2half_rn(v.z), hw = __float2half_rn(v.w);
            half lx = __float2half_rn(v.x - __half2float(hx));
            half ly = __float2half_rn(v.y - __half2float(hy));
            half lz = __float2half_rn(v.z - __half2float(hz));
            half lw = __float2half_rn(v.w - __half2float(hw));
            u32 off = (u32)(row * 144 + c4 * 8);
            sts64(hb + off, pkh2(hx, hy), pkh2(hz, hw));
            sts64(lb + off, pkh2(lx, ly), pkh2(lz, lw));
        }
    };
    auto issue_B = [&](int it, int st) {
        const int k0 = it * 64;
        const u32 s0 = sbase + st * SZ_ST + O_B;
#pragma unroll
        for (int i = 0; i < 8; i++) {
            int idx = tid + i * 256;
            int n = idx >> 3, seg = idx & 7;
            size_t go = (size_t)n * 256 + k0 + seg * 8;
            cp16(s0 + (u32)(n * 144 + seg * 16), BB + go);
        }
        cp_commit();
    };

    // ---- prologue: A(0) -> stage0, A(1) -> regs; B(0), B(1) in flight
    load_A(0);
    sts_A(0);
    load_A(1);
    issue_B(0, 0);
    issue_B(1, 1);

    for (int it = 0; it < 4; it++) {
        const int st = it % 3;
        if (it < 3) cp_wait<1>(); else cp_wait<0>();
        __syncthreads();                 // stage it ready (B cp.async + A STS)
        if (it < 2) issue_B(it + 2, (it + 2) % 3);

        const half* Ah = (const half*)(smem_raw + st * SZ_ST + O_AH);
        const half* Al = (const half*)(smem_raw + st * SZ_ST + O_AL);
        const half* Bs = (const half*)(smem_raw + st * SZ_ST + O_B);

#pragma unroll
        for (int kk = 0; kk < 4; kk++) {
            wmma::fragment<wmma::matrix_a, 16, 16, 16, half, wmma::row_major> ah[4], al[4];
            wmma::fragment<wmma::matrix_b, 16, 16, 16, half, wmma::col_major> bf[4];
#pragma unroll
            for (int mi = 0; mi < 4; mi++) {
                int r = wm * 64 + mi * 16;
                wmma::load_matrix_sync(ah[mi], Ah + r * RS + kk * 16, RS);
                wmma::load_matrix_sync(al[mi], Al + r * RS + kk * 16, RS);
            }
#pragma unroll
            for (int ni = 0; ni < 4; ni++) {
                int n = wn * 64 + ni * 16;
                wmma::load_matrix_sync(bf[ni], Bs + n * RS + kk * 16, RS);
            }
#pragma unroll
            for (int mi = 0; mi < 4; mi++)
#pragma unroll
                for (int ni = 0; ni < 4; ni++) {
                    wmma::mma_sync(acc[mi][ni], ah[mi], bf[ni], acc[mi][ni]);
                    wmma::mma_sync(acc[mi][ni], al[mi], bf[ni], acc[mi][ni]);
                }
        }

        // produce A for next iteration into stage (it+1)%3 (visible after next sync);
        // then prefetch A(it+2) into regs (latency covered by next iteration's MMAs)
        if (it < 3) {
            sts_A((it + 1) % 3);
            if (it < 2) load_A(it + 2);
        }
    }
    __syncthreads();   // all warps done with stage reads before Cs aliases them

    // ---- stage buffers dead; alias Cs[128][256] over them
#pragma unroll
    for (int mi = 0; mi < 4; mi++)
#pragma unroll
        for (int ni = 0; ni < 4; ni++)
            wmma::store_matrix_sync(Cs + (size_t)(wm * 64 + mi * 16) * 256 + wn * 64 + ni * 16,
                                    acc[mi][ni], 256, wmma::mem_row_major);
    __syncthreads();

    if (mode == 1) {
        float* Cb = C + (size_t)b * sC + (size_t)l0 * 256;
#pragma unroll
        for (int i = 0; i < 32; i++) {
            int idx = tid + i * 256;
            int row = idx >> 6, c4 = idx & 63;
            float4 v = *(const float4*)(Cs + (size_t)row * 256 + c4 * 4);
            float4 bb = __ldg((const float4*)(bias + c4 * 4));
            v.x += bb.x; v.y += bb.y; v.z += bb.z; v.w += bb.w;
            *(float4*)(Cb + (size_t)row * 256 + c4 * 4) = v;
        }
        return;
    }

    // ---- mode 0: exp in-place on K half (cols 0..127)
#pragma unroll
    for (int i = 0; i < 16; i++) {
        int idx = tid + i * 256;                  // 4096 float4 slots over 128x128
        int row = idx >> 5, c4 = idx & 31;
        float4 v = *(const float4*)(Cs + (size_t)row * 256 + c4 * 4);
        v.x = expf(v.x); v.y = expf(v.y); v.z = expf(v.z); v.w = expf(v.w);
        *(float4*)(Cs + (size_t)row * 256 + c4 * 4) = v;
    }
    __syncthreads();

    // ---- per-CTA partial S[h][d][e] (fp32, f32x2 packed) + Z[h][d]
    {
        const int h = tid >> 6;
        const int q = tid & 63;
        const int d0 = (q >> 3) * 4;
        const int e0 = (q & 7) * 4;
        ull acc2[4][2];
#pragma unroll
        for (int i = 0; i < 4; i++) { acc2[i][0] = 0ULL; acc2[i][1] = 0ULL; }
        ull z01 = 0ULL, z23 = 0ULL;

#pragma unroll 4
        for (int l = 0; l < 128; l++) {
            float4 ek = *(const float4*)(Cs + (size_t)l * 256 + h * 32 + d0);
            float4 vv = *(const float4*)(Cs + (size_t)l * 256 + 128 + h * 32 + e0);
            ull v01 = pk2(vv.x, vv.y), v23 = pk2(vv.z, vv.w);
            float ea[4] = { ek.x, ek.y, ek.z, ek.w };
#pragma unroll
            for (int i = 0; i < 4; i++) {
                ull ap = pk2(ea[i], ea[i]);
                acc2[i][0] = fma2(ap, v01, acc2[i][0]);
                acc2[i][1] = fma2(ap, v23, acc2[i][1]);
            }
            z01 = add2(z01, pk2(ek.x, ek.y));
            z23 = add2(z23, pk2(ek.z, ek.w));
        }

        float* Sp = g_Sp + (((size_t)(b * 4 + h) * 64 + blockIdx.x) * 1024);
#pragma unroll
        for (int i = 0; i < 4; i++) {
            float s0, s1, s2, s3;
            upk2(acc2[i][0], s0, s1); upk2(acc2[i][1], s2, s3);
            *(float4*)(Sp + (d0 + i) * 32 + e0) = make_float4(s0, s1, s2, s3);
        }
        if (e0 == 0) {
            float z0, z1, z2, z3;
            upk2(z01, z0, z1); upk2(z23, z2, z3);
            float* Zp = g_Zp + ((size_t)(b * 4 + h) * 64 + blockIdx.x) * 32;
            *(float4*)(Zp + d0) = make_float4(z0, z1, z2, z3);
        }
    }
}

// ---------------- prep: Wkv^T fp16 ----------------
__global__ void prep_w1(const float* __restrict__ Wqkv)
{
    const int n = blockIdx.x, k = threadIdx.x;
    g_W1[n * 256 + k] = __float2half_rn(Wqkv[k * QKV_LD + 128 + n]);
}

// ---------------- prep: N[b]^T fp16 (tiled transpose) ----------------
__global__ void tsplit()
{
    const int b = blockIdx.z;
    const int i0 = blockIdx.y * 32, j0 = blockIdx.x * 32;
    const int tx = threadIdx.x, ty = threadIdx.y;
    __shared__ float t[32][33];
    const float* Nb = g_N + (size_t)b * 65536;
#pragma unroll
    for (int r = ty; r < 32; r += 8)
        t[r][tx] = Nb[(size_t)(i0 + r) * 256 + j0 + tx];
    __syncthreads();
    half* W = g_W3 + (size_t)b * 65536;
#pragma unroll
    for (int r = ty; r < 32; r += 8)
        W[(size_t)(j0 + r) * 256 + i0 + tx] = __float2half_rn(t[tx][r]);
}

// ---------------- small fp32 GEMM (N[b] = scale * Wq @ M[b]) ----------------
__global__ void __launch_bounds__(256) gemm_f32x2(
    const float* __restrict__ A, int lda, long long sA,
    const float* __restrict__ B, int ldb, long long sB,
    float* __restrict__ C, int ldc, long long sC,
    int K, float scale)
{
    const int b = blockIdx.z;
    A += (size_t)b * sA + (size_t)blockIdx.y * 128 * lda;
    B += (size_t)b * sB;
    C += (size_t)b * sC + (size_t)blockIdx.y * 128 * ldc + blockIdx.x * 128;
    const int n0 = blockIdx.x * 128;

    __shared__ float As[16][128];
    __shared__ float Bs[16][128];
    const int tid = threadIdx.x;
    const int tx = tid & 15;
    const int ty = tid >> 4;

    ull acc[8][4];
#pragma unroll
    for (int m = 0; m < 8; m++)
#pragma unroll
        for (int p = 0; p < 4; p++) acc[m][p] = 0ULL;

    for (int k0 = 0; k0 < K; k0 += 16) {
#pragma unroll
        for (int i = 0; i < 2; i++) {
            int f = tid + i * 256;
            int row = f >> 2, c4 = (f & 3) * 4;
            float4 av = *(const float4*)(A + (size_t)row * lda + k0 + c4);
            As[c4 + 0][row] = av.x; As[c4 + 1][row] = av.y;
            As[c4 + 2][row] = av.z; As[c4 + 3][row] = av.w;
        }
#pragma unroll
        for (int i = 0; i < 2; i++) {
            int f = tid + i * 256;
            int row = f >> 5, c = (f & 31) * 4;
            *(float4*)(&Bs[row][c]) = *(const float4*)(B + (size_t)(k0 + row) * ldb + n0 + c);
        }
        __syncthreads();
#pragma unroll
        for (int kk = 0; kk < 16; kk++) {
            float4 a0 = *(const float4*)(&As[kk][ty * 4]);
            float4 a1 = *(const float4*)(&As[kk][64 + ty * 4]);
            float4 b0 = *(const float4*)(&Bs[kk][tx * 4]);
            float4 b1 = *(const float4*)(&Bs[kk][64 + tx * 4]);
            ull bp[4] = { pk2(b0.x, b0.y), pk2(b0.z, b0.w), pk2(b1.x, b1.y), pk2(b1.z, b1.w) };
            float am[8] = { a0.x, a0.y, a0.z, a0.w, a1.x, a1.y, a1.z, a1.w };
#pragma unroll
            for (int m = 0; m < 8; m++) {
                ull ap = pk2(am[m], am[m]);
#pragma unroll
                for (int p = 0; p < 4; p++) acc[m][p] = fma2(ap, bp[p], acc[m][p]);
            }
        }
        __syncthreads();
    }

#pragma unroll
    for (int m = 0; m < 8; m++) {
        int row = (m < 4) ? (ty * 4 + m) : (64 + ty * 4 + m - 4);
        float c0, c1, c2, c3, c4, c5, c6, c7;
        upk2(acc[m][0], c0, c1); upk2(acc[m][1], c2, c3);
        upk2(acc[m][2], c4, c5); upk2(acc[m][3], c6, c7);
        *(float4*)(C + (size_t)row * ldc + tx * 4) =
            make_float4(c0 * scale, c1 * scale, c2 * scale, c3 * scale);
        *(float4*)(C + (size_t)row * ldc + 64 + tx * 4) =
            make_float4(c4 * scale, c5 * scale, c6 * scale, c7 * scale);
    }
}

// ---------------- context = (sum_cta S) / (sum_cta Z) ----------------
__global__ void __launch_bounds__(1024) ctx_kernel()
{
    const int h = blockIdx.x, b = blockIdx.y;
    const int t = threadIdx.x;
    const int d = t >> 5, e = t & 31;
    const float* Sp = g_Sp + (size_t)(b * 4 + h) * 64 * 1024;
    float s = 0.f;
#pragma unroll
    for (int sp = 0; sp < 64; sp++) s += Sp[sp * 1024 + t];
    __shared__ float zs[32];
    if (e == 0) {
        const float* Zp = g_Zp + (size_t)(b * 4 + h) * 64 * 32;
        float zz = 0.f;
#pragma unroll
        for (int sp = 0; sp < 64; sp++) zz += Zp[sp * 32 + d];
        zs[d] = zz;
    }
    __syncthreads();
    g_ctx[(size_t)(b * 4 + h) * 1024 + t] = s / zs[d];
}

// ---------------- M[b] ----------------
__global__ void __launch_bounds__(256) m_kernel(const float* __restrict__ Wout)
{
    const int b = blockIdx.x;
    const int h = blockIdx.y;
    const int j = threadIdx.x;
    __shared__ float cs[1024];
    for (int i = j; i < 1024; i += 256) cs[i] = g_ctx[(size_t)b * 4096 + h * 1024 + i];
    __syncthreads();
    float* Mb = g_M + (size_t)b * HID * ND;
    float w[32];
#pragma unroll
    for (int e = 0; e < 32; e++) w[e] = Wout[(h * 32 + e) * 256 + j];
    for (int d = 0; d < 32; d++) {
        float a = 0.f;
#pragma unroll
        for (int e = 0; e < 32; e++) a += cs[d * 32 + e] * w[e];
        Mb[(h * 32 + d) * 256 + j] = a;
    }
}

// ---------------- launch ----------------
extern "C" void kernel_launch(void* const* d_in, const int* in_sizes, int n_in,
                              void* d_out, int out_size)
{
    const float* x    = (const float*)d_in[0];
    const float* Wqkv = (const float*)d_in[1];
    const float* Wout = (const float*)d_in[2];
    const float* bout = (const float*)d_in[3];
    float* out = (float*)d_out;

    float *Mp, *Np;
    half *w1, *w3;
    cudaGetSymbolAddress((void**)&Mp, g_M);
    cudaGetSymbolAddress((void**)&Np, g_N);
    cudaGetSymbolAddress((void**)&w1, g_W1);
    cudaGetSymbolAddress((void**)&w3, g_W3);

    cudaFuncSetAttribute(mma_gemm, cudaFuncAttributeMaxDynamicSharedMemorySize, SMEM_DYN);

    const float scale = 0.17677669529663687f;
    const long long sX = (long long)NL * ND;

    // 1) Wkv^T fp16
    prep_w1<<<256, 256>>>(Wqkv);

    // 2) kv GEMM (in-kernel A split) + fused exp + partial S,Z
    mma_gemm<<<dim3(64, NB), 256, SMEM_DYN>>>(
        x, sX, w1, 0, nullptr, 0, nullptr, 0);

    // 3) context
    ctx_kernel<<<dim3(NH, NB), 1024>>>();

    // 4) M[b]
    m_kernel<<<dim3(NB, NH), 256>>>(Wout);

    // 5) N[b] = scale * Wq @ M[b]
    gemm_f32x2<<<dim3(2, 2, NB), 256>>>(
        Wqkv, QKV_LD, 0, Mp, ND, (long long)HID * ND,
        Np, ND, (long long)ND * ND, HID, scale);

    // 6) transpose N[b] -> fp16
    tsplit<<<dim3(8, 8, NB), dim3(32, 8)>>>();

    // 7) out = x @ N[b] + b_out (in-kernel A split)
    mma_gemm<<<dim3(64, NB), 256, SMEM_DYN>>>(
        x, sX, w3, 65536, out, sX, bout, 1);
}